// round 5
// baseline (speedup 1.0000x reference)
#include <cuda_runtime.h>
#include <cstdint>

// ---------------- scratch (no allocations allowed) ----------------
#define CAP    65536
#define NSAMP  16384
#define SRANK  8
#define KSEL   128

__device__ unsigned int       g_skeys[NSAMP];
__device__ int                g_cnt;
__device__ int                g_t;
__device__ float              g_tr[512];
__device__ unsigned long long g_cand[CAP];
__device__ int                g_qsel[KSEL];
__device__ int                g_tok[KSEL];
__device__ float              g_topp[KSEL];
__device__ float              g_loc[KSEL];

// ---------------- helpers ----------------
__device__ __forceinline__ unsigned int okey(float f) {
    unsigned int u = __float_as_uint(f);
    return (u & 0x80000000u) ? ~u : (u | 0x80000000u);
}
__device__ __forceinline__ float fromKey(unsigned int k) {
    unsigned int u = (k & 0x80000000u) ? (k ^ 0x80000000u) : ~k;
    return __uint_as_float(u);
}

// Find bin (scanning from the TOP) where cumulative count reaches `rank`.
// res[0] = bin index, res[1] = count strictly above that bin.
// Must be called by ALL threads of the block.
__device__ void find_bin(const unsigned int* hist, int NB, int rank,
                         unsigned int* scanbuf, int* res) {
    int tid = threadIdx.x, bd = blockDim.x;
    int chunk = (NB + bd - 1) / bd;
    int base = tid * chunk;
    unsigned int s = 0;
    if (base < NB) {
        for (int j = 0; j < chunk; j++) {
            int bin = NB - 1 - (base + j);
            if (bin >= 0) s += hist[bin];
        }
    }
    scanbuf[tid] = s;
    __syncthreads();
    for (int off = 1; off < bd; off <<= 1) {
        unsigned int add = (tid >= off) ? scanbuf[tid - off] : 0u;
        __syncthreads();
        scanbuf[tid] += add;
        __syncthreads();
    }
    unsigned int inc = scanbuf[tid];
    unsigned int excl = inc - s;
    if (base < NB && excl < (unsigned)rank && (unsigned)rank <= inc) {
        unsigned int c = excl;
        for (int j = 0; j < chunk; j++) {
            int bin = NB - 1 - (base + j);
            if (bin < 0) break;
            c += hist[bin];
            if (c >= (unsigned)rank) {
                res[0] = bin;
                res[1] = (int)(c - hist[bin]);
                break;
            }
        }
    }
    __syncthreads();
}

// ---- kernel A: sample + 2-level threshold refine + per-row thresholds ----
__global__ void k_prep(const float* __restrict__ lp, const float* __restrict__ bsum,
                       const int* tptr, int B, int V) {
    __shared__ unsigned int hist[4096];
    __shared__ unsigned int scanbuf[1024];
    __shared__ int res[2];
    int tid = threadIdx.x, bd = blockDim.x;
    int t = tptr ? *tptr : 64;
    int rows = (t >= 1) ? B : 1;

    for (int i = tid; i < 4096; i += bd) hist[i] = 0;
    if (tid == 0) { res[0] = 0; res[1] = 0; }
    __syncthreads();

    // sample NSAMP evenly-strided elements, 12-bit histogram of ordered keys
    unsigned long long span = (unsigned long long)rows * (unsigned)V;
    for (int s = tid; s < NSAMP; s += bd) {
        unsigned long long idx = ((unsigned long long)s * span) >> 14;  // NSAMP=2^14
        int q = (int)(idx / (unsigned)V);
        int v = (int)(idx - (unsigned long long)q * (unsigned)V);
        float x = lp[idx];
        if (v == V - 1) x -= 1000.0f;
        unsigned int key = okey(bsum[q] + x);
        g_skeys[s] = key;
        atomicAdd(&hist[key >> 20], 1u);
    }
    __syncthreads();
    find_bin(hist, 4096, SRANK, scanbuf, res);
    int b1 = res[0];
    int above1 = res[1];
    __syncthreads();

    // refine: next 8 key bits within bin b1
    for (int i = tid; i < 256; i += bd) hist[i] = 0;
    if (tid == 0) { res[0] = 0; res[1] = 0; }
    __syncthreads();
    for (int s = tid; s < NSAMP; s += bd) {
        unsigned int key = g_skeys[s];
        if ((int)(key >> 20) == b1)
            atomicAdd(&hist[(key >> 12) & 0xFFu], 1u);
    }
    __syncthreads();
    find_bin(hist, 256, SRANK - above1, scanbuf, res);
    int b2 = res[0];
    __syncthreads();

    float tv = fromKey(((unsigned)b1 << 20) | ((unsigned)b2 << 12));
    for (int q = tid; q < B; q += bd) {
        float tr;
        if (q < rows) {
            tr = tv - bsum[q];
            tr -= (fabsf(tr) * 1e-5f + 1e-4f);    // conservative float margin
        } else {
            tr = 3.4e38f;
        }
        g_tr[q] = tr;
    }
    if (tid == 0) { g_cnt = 0; g_t = t; }
}

// ---------------- kernel B: the heavy streaming filter ----------------
// ebase is the GLOBAL element index of x.x; rowBase = row*V.
__device__ __forceinline__ void scan4(float4 x, int ebase, float tr, float s,
                                      int rowBase, int V) {
    float xs[4] = {x.x, x.y, x.z, x.w};
#pragma unroll
    for (int j = 0; j < 4; j++) {
        if (xs[j] > tr) {
            int flat = ebase + j;            // global flat index, = rowBase + v
            int v = flat - rowBase;          // row-local column
            float px = xs[j];
            if (v == V - 1) px -= 1000.0f;   // exact, same rounding order as ref
            float g = s + px;
            unsigned long long pack =
                ((unsigned long long)okey(g) << 32) |
                (unsigned int)(~(unsigned)flat);
            int pos = atomicAdd(&g_cnt, 1);
            if (pos < CAP) g_cand[pos] = pack;
        }
    }
}

__device__ __forceinline__ float max4(float4 a) {
    return fmaxf(fmaxf(a.x, a.y), fmaxf(a.z, a.w));
}

// Each block owns a flat chunk of float4 indices; chunk may span 2+ rows.
__global__ void __launch_bounds__(256) k_filter(const float* __restrict__ lp,
                                                const float* __restrict__ bsum,
                                                int V, int n4row, int total4, int chunk) {
    int tid = threadIdx.x, bd = blockDim.x;
    int s0 = blockIdx.x * chunk;
    int e0 = min(s0 + chunk, total4);
    if (s0 >= e0) return;
    int row = s0 / n4row;

    while (s0 < e0) {
        int rowEnd = (row + 1) * n4row;
        int re = min(e0, rowEnd);
        float tr = g_tr[row];
        if (tr < 3.0e38f) {
            float s = bsum[row];
            int rowBase = row * V;
            const float4* __restrict__ base = reinterpret_cast<const float4*>(lp);
            int i = s0 + tid;
            // 8-deep front-batched loads: MLP 8 per thread
            for (; i + 7 * bd < re; i += 8 * bd) {
                float4 x0 = __ldcs(base + i);
                float4 x1 = __ldcs(base + i + bd);
                float4 x2 = __ldcs(base + i + 2 * bd);
                float4 x3 = __ldcs(base + i + 3 * bd);
                float4 x4 = __ldcs(base + i + 4 * bd);
                float4 x5 = __ldcs(base + i + 5 * bd);
                float4 x6 = __ldcs(base + i + 6 * bd);
                float4 x7 = __ldcs(base + i + 7 * bd);
                float m01 = fmaxf(max4(x0), max4(x1));
                float m23 = fmaxf(max4(x2), max4(x3));
                float m45 = fmaxf(max4(x4), max4(x5));
                float m67 = fmaxf(max4(x6), max4(x7));
                float m = fmaxf(fmaxf(m01, m23), fmaxf(m45, m67));
                if (m > tr) {
                    scan4(x0, 4 * i,            tr, s, rowBase, V);
                    scan4(x1, 4 * (i + bd),     tr, s, rowBase, V);
                    scan4(x2, 4 * (i + 2 * bd), tr, s, rowBase, V);
                    scan4(x3, 4 * (i + 3 * bd), tr, s, rowBase, V);
                    scan4(x4, 4 * (i + 4 * bd), tr, s, rowBase, V);
                    scan4(x5, 4 * (i + 5 * bd), tr, s, rowBase, V);
                    scan4(x6, 4 * (i + 6 * bd), tr, s, rowBase, V);
                    scan4(x7, 4 * (i + 7 * bd), tr, s, rowBase, V);
                }
            }
            for (; i < re; i += bd) {
                float4 a = __ldcs(base + i);
                if (max4(a) > tr) scan4(a, 4 * i, tr, s, rowBase, V);
            }
        }
        s0 = re;
        row++;
    }
}

// ---------------- kernel C: exact top-128 selection ----------------
__global__ void k_select(const float* __restrict__ lp, int V, int totalElems) {
    __shared__ unsigned int hist[4096];
    __shared__ unsigned int scanbuf[512];
    __shared__ int res[2];
    __shared__ int cnt;
    __shared__ unsigned long long sbuf[512];
    int tid = threadIdx.x, bd = blockDim.x;
    int C = min(g_cnt, CAP);

    // phase 1: 12-bit histogram of candidate keys
    for (int i = tid; i < 4096; i += bd) hist[i] = 0;
    if (tid == 0) { res[0] = 0; res[1] = 0; cnt = 0; }
    __syncthreads();
    for (int i = tid; i < C; i += bd)
        atomicAdd(&hist[(unsigned int)(g_cand[i] >> 52)], 1u);
    __syncthreads();
    find_bin(hist, 4096, KSEL, scanbuf, res);
    int b1 = res[0];
    int above1 = res[1];
    __syncthreads();

    // phase 2: refine inside bin b1 with next 8 key bits
    for (int i = tid; i < 256; i += bd) hist[i] = 0;
    if (tid == 0) { res[0] = 0; res[1] = 0; }
    __syncthreads();
    for (int i = tid; i < C; i += bd) {
        unsigned long long c = g_cand[i];
        if ((unsigned int)(c >> 52) == (unsigned)b1)
            atomicAdd(&hist[(unsigned int)(c >> 44) & 0xFFu], 1u);
    }
    __syncthreads();
    find_bin(hist, 256, KSEL - above1, scanbuf, res);
    int b2 = res[0];
    __syncthreads();
    unsigned int P = ((unsigned int)b1 << 8) | (unsigned int)b2;  // 20-bit prefix

    // phase 3: collect finalists
    for (int i = tid; i < C; i += bd) {
        unsigned long long c = g_cand[i];
        if ((unsigned int)(c >> 44) >= P) {
            int p = atomicAdd(&cnt, 1);
            if (p < 512) sbuf[p] = c;
        }
    }
    __syncthreads();
    int M = min(cnt, 512);
    int n = (M <= 128) ? 128 : ((M <= 256) ? 256 : 512);
    for (int i = tid; i < n; i += bd)
        if (i >= M) sbuf[i] = 0ULL;
    __syncthreads();

    // bitonic sort descending (value desc, then flat-index asc via ~flat)
    for (int k = 2; k <= n; k <<= 1) {
        for (int j = k >> 1; j > 0; j >>= 1) {
            for (int i = tid; i < n; i += bd) {
                int l = i ^ j;
                if (l > i) {
                    unsigned long long a = sbuf[i], b = sbuf[l];
                    bool up = ((i & k) == 0);
                    if (up == (a < b)) { sbuf[i] = b; sbuf[l] = a; }
                }
            }
            __syncthreads();
        }
    }

    if (tid < KSEL) {
        unsigned long long c = sbuf[tid];
        unsigned int key = (unsigned int)(c >> 32);
        unsigned int flat = ~((unsigned int)c);
        if (flat >= (unsigned)totalElems) flat = 0;   // defensive (padding)
        int q = (int)(flat / (unsigned)V);
        int v = (int)(flat - (unsigned)q * (unsigned)V);
        g_qsel[tid] = q;
        g_tok[tid]  = v;
        g_topp[tid] = fromKey(key);
        float x = lp[(size_t)flat];
        if (v == V - 1) x -= 1000.0f;
        g_loc[tid] = x;
    }
}

// ---------------- kernel D: gather + write all output sections ----------------
__global__ void k_write(const int* __restrict__ bseq, const float* __restrict__ bseqlp,
                        const float* __restrict__ sh, const float* __restrict__ sc,
                        float* __restrict__ out,
                        int T, int B, int S, int H, int total) {
    int idx = blockIdx.x * blockDim.x + threadIdx.x;
    if (idx >= total) return;
    int t = g_t;
    int TB = T * B;
    int BH = B * H;
    float val = 0.0f;
    if (idx < TB) {                               // new_seq (int -> float)
        int i = idx / B, b = idx - i * B;
        int srcv;
        if (i < t)       srcv = bseq[i * B + g_qsel[b]];
        else if (i == t) srcv = g_tok[b];
        else             srcv = bseq[idx];
        val = (float)srcv;
    } else if (idx < 2 * TB) {                    // new_logps
        int r = idx - TB;
        int i = r / B, b = r - i * B;
        if (i < t)       val = bseqlp[i * B + g_qsel[b]];
        else if (i == t) val = g_loc[b];
        else             val = bseqlp[r];
    } else if (idx < 2 * TB + B) {                // new_sum
        val = g_topp[idx - 2 * TB];
    } else if (idx < 2 * TB + B + S) {            // new_h
        int r = idx - (2 * TB + B);
        int l = r / BH;
        int bh = r - l * BH;
        int b = bh / H, h = bh - b * H;
        val = sh[(size_t)l * BH + (size_t)g_qsel[b] * H + h];
    } else {                                      // new_c
        int r = idx - (2 * TB + B + S);
        int l = r / BH;
        int bh = r - l * BH;
        int b = bh / H, h = bh - b * H;
        val = sc[(size_t)l * BH + (size_t)g_qsel[b] * H + h];
    }
    out[idx] = val;
}

// ---------------- launch ----------------
extern "C" void kernel_launch(void* const* d_in, const int* in_sizes, int n_in,
                              void* d_out, int out_size) {
    const float* lp     = (const float*)d_in[0];   // (B, V)
    const int*   bseq   = (const int*)  d_in[1];   // (T, B)
    const float* bseqlp = (const float*)d_in[2];   // (T, B)
    const float* bsum   = (const float*)d_in[3];   // (B,)
    const float* sh     = (const float*)d_in[4];   // (L, B, H)
    const float* sc     = (const float*)d_in[5];   // (L, B, H)
    const int*   tptr   = (n_in > 6) ? (const int*)d_in[6] : nullptr;

    int B = in_sizes[3];
    int V = in_sizes[0] / B;
    int T = in_sizes[1] / B;
    int S = in_sizes[4];          // L*B*H
    int H = 1024;                 // fixed for this problem shape

    int n4row  = V >> 2;
    int total4 = B * n4row;
    const int G = 592;            // 4 blocks/SM, one balanced wave on 148 SMs
    int chunk = (total4 + G - 1) / G;

    k_prep  <<<1, 1024>>>(lp, bsum, tptr, B, V);
    k_filter<<<G, 256>>>(lp, bsum, V, n4row, total4, chunk);
    k_select<<<1, 512>>>(lp, V, B * V);

    int total = out_size;
    k_write<<<(total + 255) / 256, 256>>>(bseq, bseqlp, sh, sc,
                                          (float*)d_out, T, B, S, H, total);
}

// round 10
// speedup vs baseline: 1.4633x; 1.4633x over previous
#include <cuda_runtime.h>
#include <cstdint>

// ---------------- scratch (no allocations allowed) ----------------
#define CAP    65536
#define NSAMP  16384
#define SRANK  8
#define KSEL   128
#define TILE4  1024      // float4 per tile = 16KB
#define GFILT  592

__device__ int                g_cnt;
__device__ int                g_t;
__device__ float              g_tr[512];
__device__ unsigned long long g_cand[CAP];
__device__ int                g_qsel[KSEL];
__device__ int                g_tok[KSEL];
__device__ float              g_topp[KSEL];
__device__ float              g_loc[KSEL];

// ---------------- helpers ----------------
__device__ __forceinline__ unsigned int okey(float f) {
    unsigned int u = __float_as_uint(f);
    return (u & 0x80000000u) ? ~u : (u | 0x80000000u);
}
__device__ __forceinline__ float fromKey(unsigned int k) {
    unsigned int u = (k & 0x80000000u) ? (k ^ 0x80000000u) : ~k;
    return __uint_as_float(u);
}
__device__ __forceinline__ uint32_t s2u(const void* p) {
    uint32_t a;
    asm("{ .reg .u64 t; cvta.to.shared.u64 t, %1; cvt.u32.u64 %0, t; }"
        : "=r"(a) : "l"(p));
    return a;
}
__device__ __forceinline__ void mbar_init(uint32_t addr, uint32_t count) {
    asm volatile("mbarrier.init.shared.b64 [%0], %1;" :: "r"(addr), "r"(count) : "memory");
}
__device__ __forceinline__ void mbar_expect_tx(uint32_t addr, uint32_t bytes) {
    asm volatile("mbarrier.arrive.expect_tx.shared.b64 _, [%0], %1;"
                 :: "r"(addr), "r"(bytes) : "memory");
}
__device__ __forceinline__ void bulk_g2s(uint32_t dst, const void* src,
                                         uint32_t bytes, uint32_t mbar) {
    asm volatile("cp.async.bulk.shared::cta.global.mbarrier::complete_tx::bytes "
                 "[%0], [%1], %2, [%3];"
                 :: "r"(dst), "l"(src), "r"(bytes), "r"(mbar) : "memory");
}
__device__ __forceinline__ void mbar_wait(uint32_t addr, uint32_t parity) {
    asm volatile(
        "{\n\t"
        ".reg .pred P;\n\t"
        "LW%=:\n\t"
        "mbarrier.try_wait.parity.acquire.cta.shared::cta.b64 P, [%0], %1, 0x989680;\n\t"
        "@P bra LD%=;\n\t"
        "bra LW%=;\n\t"
        "LD%=:\n\t"
        "}"
        :: "r"(addr), "r"(parity) : "memory");
}

// Find bin (scanning from the TOP) where cumulative count reaches `rank`.
// res[0] = bin index, res[1] = count strictly above that bin.
__device__ void find_bin(const unsigned int* hist, int NB, int rank,
                         unsigned int* scanbuf, int* res) {
    int tid = threadIdx.x, bd = blockDim.x;
    int chunk = (NB + bd - 1) / bd;
    int base = tid * chunk;
    unsigned int s = 0;
    if (base < NB) {
        for (int j = 0; j < chunk; j++) {
            int bin = NB - 1 - (base + j);
            if (bin >= 0) s += hist[bin];
        }
    }
    scanbuf[tid] = s;
    __syncthreads();
    for (int off = 1; off < bd; off <<= 1) {
        unsigned int add = (tid >= off) ? scanbuf[tid - off] : 0u;
        __syncthreads();
        scanbuf[tid] += add;
        __syncthreads();
    }
    unsigned int inc = scanbuf[tid];
    unsigned int excl = inc - s;
    if (base < NB && excl < (unsigned)rank && (unsigned)rank <= inc) {
        unsigned int c = excl;
        for (int j = 0; j < chunk; j++) {
            int bin = NB - 1 - (base + j);
            if (bin < 0) break;
            c += hist[bin];
            if (c >= (unsigned)rank) {
                res[0] = bin;
                res[1] = (int)(c - hist[bin]);
                break;
            }
        }
    }
    __syncthreads();
}

// ---- kernel A: sample + 2-level threshold refine + per-row thresholds ----
__global__ void k_prep(const float* __restrict__ lp, const float* __restrict__ bsum,
                       const int* tptr, int B, int V) {
    __shared__ unsigned int hist[4096];
    __shared__ unsigned int scanbuf[1024];
    __shared__ int res[2];
    int tid = threadIdx.x, bd = blockDim.x;   // bd = 1024
    int t = tptr ? *tptr : 64;
    int rows = (t >= 1) ? B : 1;

    for (int i = tid; i < 4096; i += bd) hist[i] = 0;
    if (tid == 0) { res[0] = 0; res[1] = 0; }
    __syncthreads();

    // 16 samples per thread, all loads batched (independent)
    unsigned long long span = (unsigned long long)rows * (unsigned)V;
    unsigned int keys[16];
    float xs[16];
    int vcol[16];
    int qrow[16];
#pragma unroll
    for (int u = 0; u < 16; u++) {
        int s = tid + u * 1024;
        unsigned long long idx = ((unsigned long long)s * span) >> 14;  // NSAMP=2^14
        int q = (int)(idx / (unsigned)V);
        int v = (int)(idx - (unsigned long long)q * (unsigned)V);
        qrow[u] = q; vcol[u] = v;
        xs[u] = __ldg(&lp[idx]);
    }
#pragma unroll
    for (int u = 0; u < 16; u++) {
        float x = xs[u];
        if (vcol[u] == V - 1) x -= 1000.0f;
        keys[u] = okey(bsum[qrow[u]] + x);
        atomicAdd(&hist[keys[u] >> 20], 1u);
    }
    __syncthreads();
    find_bin(hist, 4096, SRANK, scanbuf, res);
    int b1 = res[0];
    int above1 = res[1];
    __syncthreads();

    // refine: next 8 key bits within bin b1
    for (int i = tid; i < 256; i += bd) hist[i] = 0;
    if (tid == 0) { res[0] = 0; res[1] = 0; }
    __syncthreads();
#pragma unroll
    for (int u = 0; u < 16; u++) {
        if ((int)(keys[u] >> 20) == b1)
            atomicAdd(&hist[(keys[u] >> 12) & 0xFFu], 1u);
    }
    __syncthreads();
    find_bin(hist, 256, SRANK - above1, scanbuf, res);
    int b2 = res[0];
    __syncthreads();

    float tv = fromKey(((unsigned)b1 << 20) | ((unsigned)b2 << 12));
    for (int q = tid; q < B; q += bd) {
        float tr;
        if (q < rows) {
            tr = tv - bsum[q];
            tr -= (fabsf(tr) * 1e-5f + 1e-4f);    // conservative float margin
        } else {
            tr = 3.4e38f;
        }
        g_tr[q] = tr;
    }
    if (tid == 0) { g_cnt = 0; g_t = t; }
}

// ---------------- kernel B: TMA double-buffered streaming filter ----------------
// ebase is the GLOBAL element index of x.x; rowBase = row*V.
__device__ __forceinline__ void scan4(float4 x, int ebase, float tr, float s,
                                      int rowBase, int V) {
    float xs4[4] = {x.x, x.y, x.z, x.w};
#pragma unroll
    for (int j = 0; j < 4; j++) {
        if (xs4[j] > tr) {
            int flat = ebase + j;            // = rowBase + v
            int v = flat - rowBase;
            float px = xs4[j];
            if (v == V - 1) px -= 1000.0f;   // exact, same rounding order as ref
            float g = s + px;
            unsigned long long pack =
                ((unsigned long long)okey(g) << 32) |
                (unsigned int)(~(unsigned)flat);
            int pos = atomicAdd(&g_cnt, 1);
            if (pos < CAP) g_cand[pos] = pack;
        }
    }
}
__device__ __forceinline__ float max4(float4 a) {
    return fmaxf(fmaxf(a.x, a.y), fmaxf(a.z, a.w));
}

__global__ void __launch_bounds__(256) k_filter(const float* __restrict__ lp,
                                                const float* __restrict__ bsum,
                                                int V, int n4row, int total4, int nTiles) {
    __shared__ __align__(16) float4 buf[2][TILE4];     // 2 x 16KB
    __shared__ __align__(8) unsigned long long mbar[2];
    int tid = threadIdx.x;
    int bid = blockIdx.x;
    int G   = gridDim.x;

    uint32_t m0 = s2u(&mbar[0]);
    uint32_t m1 = s2u(&mbar[1]);
    uint32_t bs0 = s2u(&buf[0][0]);
    uint32_t bs1 = s2u(&buf[1][0]);
    const float4* gbase = reinterpret_cast<const float4*>(lp);

    if (tid == 0) {
        mbar_init(m0, 1);
        mbar_init(m1, 1);
        asm volatile("fence.proxy.async.shared::cta;" ::: "memory");
    }
    __syncthreads();

    // prologue: issue tiles bid (buf0) and bid+G (buf1)
    if (tid == 0) {
        if (bid < nTiles) {
            int tb4 = bid * TILE4;
            uint32_t bytes = (uint32_t)(min(TILE4, total4 - tb4)) * 16u;
            mbar_expect_tx(m0, bytes);
            bulk_g2s(bs0, gbase + tb4, bytes, m0);
        }
        int t1 = bid + G;
        if (t1 < nTiles) {
            int tb4 = t1 * TILE4;
            uint32_t bytes = (uint32_t)(min(TILE4, total4 - tb4)) * 16u;
            mbar_expect_tx(m1, bytes);
            bulk_g2s(bs1, gbase + tb4, bytes, m1);
        }
    }

    int k = 0;
    for (int t = bid; t < nTiles; t += G, k++) {
        int bb  = k & 1;
        int par = (k >> 1) & 1;
        mbar_wait(bb ? m1 : m0, (uint32_t)par);

        int tb4  = t * TILE4;
        int cnt4 = min(TILE4, total4 - tb4);
        int r0   = tb4 / n4row;                 // once per tile
        int re4  = (r0 + 1) * n4row;
        float tr0 = g_tr[r0];
        float sv0 = bsum[r0];
        float tr1 = tr0, sv1 = sv0;
        if (re4 < tb4 + cnt4) { tr1 = g_tr[r0 + 1]; sv1 = bsum[r0 + 1]; }

        const float4* sb = buf[bb];
#pragma unroll
        for (int u = 0; u < 4; u++) {
            int idx = tid + u * 256;
            if (idx < cnt4) {
                float4 x = sb[idx];
                int f4 = tb4 + idx;
                bool sec = (f4 >= re4);
                float tr = sec ? tr1 : tr0;
                if (max4(x) > tr) {
                    int row = sec ? (r0 + 1) : r0;
                    scan4(x, 4 * f4, tr, sec ? sv1 : sv0, row * V, V);
                }
            }
        }
        __syncthreads();   // all threads done reading buf[bb]
        if (tid == 0) {
            int tn = t + 2 * G;
            if (tn < nTiles) {
                int tb = tn * TILE4;
                uint32_t bytes = (uint32_t)(min(TILE4, total4 - tb)) * 16u;
                uint32_t mb = bb ? m1 : m0;
                mbar_expect_tx(mb, bytes);
                bulk_g2s(bb ? bs1 : bs0, gbase + tb, bytes, mb);
            }
        }
    }
}

// ---------------- kernel C: exact top-128 selection ----------------
__global__ void k_select(const float* __restrict__ lp, int V, int totalElems) {
    __shared__ unsigned int hist[4096];
    __shared__ unsigned int scanbuf[1024];
    __shared__ int res[2];
    __shared__ int cnt;
    __shared__ unsigned long long sbuf[512];
    int tid = threadIdx.x, bd = blockDim.x;    // bd = 1024
    int C = min(g_cnt, CAP);

    // phase 1: 12-bit histogram of candidate keys
    for (int i = tid; i < 4096; i += bd) hist[i] = 0;
    if (tid == 0) { res[0] = 0; res[1] = 0; cnt = 0; }
    __syncthreads();
    for (int i = tid; i < C; i += bd)
        atomicAdd(&hist[(unsigned int)(g_cand[i] >> 52)], 1u);
    __syncthreads();
    find_bin(hist, 4096, KSEL, scanbuf, res);
    int b1 = res[0];
    int above1 = res[1];
    __syncthreads();

    // phase 2: refine inside bin b1 with next 8 key bits
    for (int i = tid; i < 256; i += bd) hist[i] = 0;
    if (tid == 0) { res[0] = 0; res[1] = 0; }
    __syncthreads();
    for (int i = tid; i < C; i += bd) {
        unsigned long long c = g_cand[i];
        if ((unsigned int)(c >> 52) == (unsigned)b1)
            atomicAdd(&hist[(unsigned int)(c >> 44) & 0xFFu], 1u);
    }
    __syncthreads();
    find_bin(hist, 256, KSEL - above1, scanbuf, res);
    int b2 = res[0];
    __syncthreads();
    unsigned int P = ((unsigned int)b1 << 8) | (unsigned int)b2;  // 20-bit prefix

    // phase 3: collect finalists
    for (int i = tid; i < C; i += bd) {
        unsigned long long c = g_cand[i];
        if ((unsigned int)(c >> 44) >= P) {
            int p = atomicAdd(&cnt, 1);
            if (p < 512) sbuf[p] = c;
        }
    }
    __syncthreads();
    int M = min(cnt, 512);
    int n = (M <= 128) ? 128 : ((M <= 256) ? 256 : 512);
    for (int i = tid; i < n; i += bd)
        if (i >= M) sbuf[i] = 0ULL;
    __syncthreads();

    // bitonic sort descending (value desc, then flat-index asc via ~flat)
    for (int k = 2; k <= n; k <<= 1) {
        for (int j = k >> 1; j > 0; j >>= 1) {
            for (int i = tid; i < n; i += bd) {
                int l = i ^ j;
                if (l > i) {
                    unsigned long long a = sbuf[i], b = sbuf[l];
                    bool up = ((i & k) == 0);
                    if (up == (a < b)) { sbuf[i] = b; sbuf[l] = a; }
                }
            }
            __syncthreads();
        }
    }

    if (tid < KSEL) {
        unsigned long long c = sbuf[tid];
        unsigned int key = (unsigned int)(c >> 32);
        unsigned int flat = ~((unsigned int)c);
        if (flat >= (unsigned)totalElems) flat = 0;   // defensive (padding)
        int q = (int)(flat / (unsigned)V);
        int v = (int)(flat - (unsigned)q * (unsigned)V);
        g_qsel[tid] = q;
        g_tok[tid]  = v;
        g_topp[tid] = fromKey(key);
        float x = lp[(size_t)flat];
        if (v == V - 1) x -= 1000.0f;
        g_loc[tid] = x;
    }
}

// ---------------- kernel D: gather + write all output sections ----------------
__global__ void k_write(const int* __restrict__ bseq, const float* __restrict__ bseqlp,
                        const float* __restrict__ sh, const float* __restrict__ sc,
                        float* __restrict__ out,
                        int T, int B, int S, int H, int total,
                        int bSh, int hSh, int bhSh) {
    int idx = blockIdx.x * blockDim.x + threadIdx.x;
    if (idx >= total) return;
    int t = g_t;
    int TB = T * B;
    int BH = B * H;
    bool pw = (bSh >= 0) && (hSh >= 0) && (bhSh >= 0);
    float val = 0.0f;
    if (idx < TB) {                               // new_seq (int -> float)
        int i = pw ? (idx >> bSh) : (idx / B);
        int b = idx - i * B;
        int srcv;
        if (i < t)       srcv = bseq[i * B + g_qsel[b]];
        else if (i == t) srcv = g_tok[b];
        else             srcv = bseq[idx];
        val = (float)srcv;
    } else if (idx < 2 * TB) {                    // new_logps
        int r = idx - TB;
        int i = pw ? (r >> bSh) : (r / B);
        int b = r - i * B;
        if (i < t)       val = bseqlp[i * B + g_qsel[b]];
        else if (i == t) val = g_loc[b];
        else             val = bseqlp[r];
    } else if (idx < 2 * TB + B) {                // new_sum
        val = g_topp[idx - 2 * TB];
    } else if (idx < 2 * TB + B + S) {            // new_h
        int r = idx - (2 * TB + B);
        int l  = pw ? (r >> bhSh) : (r / BH);
        int bh = r - l * BH;
        int b  = pw ? (bh >> hSh) : (bh / H);
        int h  = bh - b * H;
        val = sh[(size_t)l * BH + (size_t)g_qsel[b] * H + h];
    } else {                                      // new_c
        int r = idx - (2 * TB + B + S);
        int l  = pw ? (r >> bhSh) : (r / BH);
        int bh = r - l * BH;
        int b  = pw ? (bh >> hSh) : (bh / H);
        int h  = bh - b * H;
        val = sc[(size_t)l * BH + (size_t)g_qsel[b] * H + h];
    }
    out[idx] = val;
}

// ---------------- launch ----------------
static inline int ilog2_exact(int x) {
    int s = 0;
    while ((1 << s) < x) s++;
    return ((1 << s) == x) ? s : -1;
}

extern "C" void kernel_launch(void* const* d_in, const int* in_sizes, int n_in,
                              void* d_out, int out_size) {
    const float* lp     = (const float*)d_in[0];   // (B, V)
    const int*   bseq   = (const int*)  d_in[1];   // (T, B)
    const float* bseqlp = (const float*)d_in[2];   // (T, B)
    const float* bsum   = (const float*)d_in[3];   // (B,)
    const float* sh     = (const float*)d_in[4];   // (L, B, H)
    const float* sc     = (const float*)d_in[5];   // (L, B, H)
    const int*   tptr   = (n_in > 6) ? (const int*)d_in[6] : nullptr;

    int B = in_sizes[3];
    int V = in_sizes[0] / B;
    int T = in_sizes[1] / B;
    int S = in_sizes[4];          // L*B*H
    int H = 1024;                 // fixed for this problem shape

    int n4row  = V >> 2;
    int total4 = B * n4row;
    int nTiles = (total4 + TILE4 - 1) / TILE4;
    int G = GFILT < nTiles ? GFILT : nTiles;

    int bSh  = ilog2_exact(B);
    int hSh  = ilog2_exact(H);
    int bhSh = ilog2_exact(B * H);

    k_prep  <<<1, 1024>>>(lp, bsum, tptr, B, V);
    k_filter<<<G, 256>>>(lp, bsum, V, n4row, total4, nTiles);
    k_select<<<1, 1024>>>(lp, V, B * V);

    int total = out_size;
    k_write<<<(total + 255) / 256, 256>>>(bseq, bseqlp, sh, sc,
                                          (float*)d_out, T, B, S, H, total,
                                          bSh, hSh, bhSh);
}

// round 11
// speedup vs baseline: 1.6493x; 1.1271x over previous
#include <cuda_runtime.h>
#include <cstdint>

// ---------------- scratch (no allocations allowed) ----------------
#define CAP    65536
#define NSAMP  16384
#define SBLK   64        // sampling blocks (64 x 256 = NSAMP)
#define SRANK  8
#define KSEL   128
#define TILE4  1024      // float4 per tile = 16KB
#define GFILT  592

__device__ int                g_cnt;
__device__ int                g_t;
__device__ float              g_tr[512];
__device__ unsigned long long g_cand[CAP];
__device__ int                g_qsel[KSEL];
__device__ int                g_tok[KSEL];
__device__ float              g_topp[KSEL];
__device__ float              g_loc[KSEL];
// prep state (must be zero at entry; reset at end of prep for graph replays)
__device__ unsigned int       g_hist4k[4096];
__device__ unsigned int       g_hist256[256];
__device__ int                g_c1, g_c2;
__device__ int                g_phase1;
__device__ int                g_b1v, g_ab1v;

// ---------------- helpers ----------------
__device__ __forceinline__ unsigned int okey(float f) {
    unsigned int u = __float_as_uint(f);
    return (u & 0x80000000u) ? ~u : (u | 0x80000000u);
}
__device__ __forceinline__ float fromKey(unsigned int k) {
    unsigned int u = (k & 0x80000000u) ? (k ^ 0x80000000u) : ~k;
    return __uint_as_float(u);
}
__device__ __forceinline__ uint32_t s2u(const void* p) {
    uint32_t a;
    asm("{ .reg .u64 t; cvta.to.shared.u64 t, %1; cvt.u32.u64 %0, t; }"
        : "=r"(a) : "l"(p));
    return a;
}
__device__ __forceinline__ void mbar_init(uint32_t addr, uint32_t count) {
    asm volatile("mbarrier.init.shared.b64 [%0], %1;" :: "r"(addr), "r"(count) : "memory");
}
__device__ __forceinline__ void mbar_expect_tx(uint32_t addr, uint32_t bytes) {
    asm volatile("mbarrier.arrive.expect_tx.shared.b64 _, [%0], %1;"
                 :: "r"(addr), "r"(bytes) : "memory");
}
__device__ __forceinline__ void bulk_g2s(uint32_t dst, const void* src,
                                         uint32_t bytes, uint32_t mbar) {
    asm volatile("cp.async.bulk.shared::cta.global.mbarrier::complete_tx::bytes "
                 "[%0], [%1], %2, [%3];"
                 :: "r"(dst), "l"(src), "r"(bytes), "r"(mbar) : "memory");
}
__device__ __forceinline__ void mbar_wait(uint32_t addr, uint32_t parity) {
    asm volatile(
        "{\n\t"
        ".reg .pred P;\n\t"
        "LW%=:\n\t"
        "mbarrier.try_wait.parity.acquire.cta.shared::cta.b64 P, [%0], %1, 0x989680;\n\t"
        "@P bra LD%=;\n\t"
        "bra LW%=;\n\t"
        "LD%=:\n\t"
        "}"
        :: "r"(addr), "r"(parity) : "memory");
}

// Find bin (scanning from the TOP) where cumulative count reaches `rank`.
// res[0] = bin index, res[1] = count strictly above that bin.
__device__ void find_bin(const unsigned int* hist, int NB, int rank,
                         unsigned int* scanbuf, int* res) {
    int tid = threadIdx.x, bd = blockDim.x;
    int chunk = (NB + bd - 1) / bd;
    int base = tid * chunk;
    unsigned int s = 0;
    if (base < NB) {
        for (int j = 0; j < chunk; j++) {
            int bin = NB - 1 - (base + j);
            if (bin >= 0) s += hist[bin];
        }
    }
    scanbuf[tid] = s;
    __syncthreads();
    for (int off = 1; off < bd; off <<= 1) {
        unsigned int add = (tid >= off) ? scanbuf[tid - off] : 0u;
        __syncthreads();
        scanbuf[tid] += add;
        __syncthreads();
    }
    unsigned int inc = scanbuf[tid];
    unsigned int excl = inc - s;
    if (base < NB && excl < (unsigned)rank && (unsigned)rank <= inc) {
        unsigned int c = excl;
        for (int j = 0; j < chunk; j++) {
            int bin = NB - 1 - (base + j);
            if (bin < 0) break;
            c += hist[bin];
            if (c >= (unsigned)rank) {
                res[0] = bin;
                res[1] = (int)(c - hist[bin]);
                break;
            }
        }
    }
    __syncthreads();
}

// ---- kernel A: distributed sample + grid-sync 2-level threshold (ONE launch) ----
// 64 blocks x 256 threads; 1 sample per thread. g_hist4k/g_hist256/g_c1/g_c2/
// g_phase1 are ZERO at entry (zero-init first call; reset at end for replays).
__global__ void __launch_bounds__(256) k_prep(const float* __restrict__ lp,
                                              const float* __restrict__ bsum,
                                              const int* tptr, int B, int V) {
    __shared__ unsigned int shist[4096];
    __shared__ unsigned int scanbuf[256];
    __shared__ int res[2];
    int tid = threadIdx.x;
    int bix = blockIdx.x;
    int t = tptr ? *tptr : 64;
    int rows = (t >= 1) ? B : 1;

    // phase A: one sample per thread, coarse 12-bit histogram via global atomics
    unsigned long long span = (unsigned long long)rows * (unsigned)V;
    int s = bix * 256 + tid;
    unsigned long long idx = ((unsigned long long)s * span) >> 14;  // NSAMP=2^14
    int q = (int)(idx / (unsigned)V);
    int v = (int)(idx - (unsigned long long)q * (unsigned)V);
    float x = __ldg(&lp[idx]);
    if (v == V - 1) x -= 1000.0f;
    unsigned int key = okey(bsum[q] + x);
    atomicAdd(&g_hist4k[key >> 20], 1u);

    __threadfence();
    __syncthreads();
    if (tid == 0) atomicAdd(&g_c1, 1);

    // block 0: wait all, compute coarse bin
    if (bix == 0) {
        if (tid == 0) { while (atomicAdd(&g_c1, 0) < SBLK) __nanosleep(64); }
        __syncthreads();
        __threadfence();
        // copy global hist to shared (vectorized)
        const uint4* gh = reinterpret_cast<const uint4*>(g_hist4k);
        uint4* sh4 = reinterpret_cast<uint4*>(shist);
        for (int i = tid; i < 1024; i += 256) sh4[i] = gh[i];
        if (tid == 0) { res[0] = 0; res[1] = 0; }
        __syncthreads();
        find_bin(shist, 4096, SRANK, scanbuf, res);
        if (tid == 0) {
            g_b1v  = res[0];
            g_ab1v = res[1];
            __threadfence();
            atomicExch(&g_phase1, 1);
        }
    }

    // all blocks: wait for phase 1 result
    if (tid == 0) { while (atomicAdd(&g_phase1, 0) == 0) __nanosleep(64); }
    __syncthreads();
    __threadfence();
    int b1 = g_b1v;

    // phase B: refine histogram (next 8 key bits) via global atomics
    if ((int)(key >> 20) == b1)
        atomicAdd(&g_hist256[(key >> 12) & 0xFFu], 1u);
    __threadfence();
    __syncthreads();
    if (tid == 0) atomicAdd(&g_c2, 1);
    if (bix != 0) return;

    // block 0: wait all, compute final threshold, write per-row thresholds, reset state
    if (tid == 0) { while (atomicAdd(&g_c2, 0) < SBLK) __nanosleep(64); }
    __syncthreads();
    __threadfence();
    for (int i = tid; i < 256; i += 256) shist[i] = g_hist256[i];
    if (tid == 0) { res[0] = 0; res[1] = 0; }
    __syncthreads();
    int ab1 = g_ab1v;
    find_bin(shist, 256, SRANK - ab1, scanbuf, res);
    int b2 = res[0];
    __syncthreads();

    float tv = fromKey(((unsigned)b1 << 20) | ((unsigned)b2 << 12));
    for (int qq = tid; qq < B; qq += 256) {
        float tr;
        if (qq < rows) {
            tr = tv - bsum[qq];
            tr -= (fabsf(tr) * 1e-5f + 1e-4f);    // conservative float margin
        } else {
            tr = 3.4e38f;
        }
        g_tr[qq] = tr;
    }
    // reset replay state to zero
    for (int i = tid; i < 4096; i += 256) g_hist4k[i] = 0;
    for (int i = tid; i < 256;  i += 256) g_hist256[i] = 0;
    if (tid == 0) {
        g_c1 = 0; g_c2 = 0; g_phase1 = 0;
        g_cnt = 0; g_t = t;
    }
}

// ---------------- kernel B: TMA double-buffered streaming filter ----------------
// ebase is the GLOBAL element index of x.x; rowBase = row*V.
__device__ __forceinline__ void scan4(float4 x, int ebase, float tr, float s,
                                      int rowBase, int V) {
    float xs4[4] = {x.x, x.y, x.z, x.w};
#pragma unroll
    for (int j = 0; j < 4; j++) {
        if (xs4[j] > tr) {
            int flat = ebase + j;            // = rowBase + v
            int v = flat - rowBase;
            float px = xs4[j];
            if (v == V - 1) px -= 1000.0f;   // exact, same rounding order as ref
            float g = s + px;
            unsigned long long pack =
                ((unsigned long long)okey(g) << 32) |
                (unsigned int)(~(unsigned)flat);
            int pos = atomicAdd(&g_cnt, 1);
            if (pos < CAP) g_cand[pos] = pack;
        }
    }
}
__device__ __forceinline__ float max4(float4 a) {
    return fmaxf(fmaxf(a.x, a.y), fmaxf(a.z, a.w));
}

__global__ void __launch_bounds__(256) k_filter(const float* __restrict__ lp,
                                                const float* __restrict__ bsum,
                                                int V, int n4row, int total4, int nTiles) {
    __shared__ __align__(16) float4 buf[2][TILE4];     // 2 x 16KB
    __shared__ __align__(8) unsigned long long mbar[2];
    int tid = threadIdx.x;
    int bid = blockIdx.x;
    int G   = gridDim.x;

    uint32_t m0 = s2u(&mbar[0]);
    uint32_t m1 = s2u(&mbar[1]);
    uint32_t bs0 = s2u(&buf[0][0]);
    uint32_t bs1 = s2u(&buf[1][0]);
    const float4* gbase = reinterpret_cast<const float4*>(lp);

    if (tid == 0) {
        mbar_init(m0, 1);
        mbar_init(m1, 1);
        asm volatile("fence.proxy.async.shared::cta;" ::: "memory");
    }
    __syncthreads();

    // prologue: issue tiles bid (buf0) and bid+G (buf1)
    if (tid == 0) {
        if (bid < nTiles) {
            int tb4 = bid * TILE4;
            uint32_t bytes = (uint32_t)(min(TILE4, total4 - tb4)) * 16u;
            mbar_expect_tx(m0, bytes);
            bulk_g2s(bs0, gbase + tb4, bytes, m0);
        }
        int t1 = bid + G;
        if (t1 < nTiles) {
            int tb4 = t1 * TILE4;
            uint32_t bytes = (uint32_t)(min(TILE4, total4 - tb4)) * 16u;
            mbar_expect_tx(m1, bytes);
            bulk_g2s(bs1, gbase + tb4, bytes, m1);
        }
    }

    int k = 0;
    for (int t = bid; t < nTiles; t += G, k++) {
        int bb  = k & 1;
        int par = (k >> 1) & 1;
        mbar_wait(bb ? m1 : m0, (uint32_t)par);

        int tb4  = t * TILE4;
        int cnt4 = min(TILE4, total4 - tb4);
        int r0   = tb4 / n4row;                 // once per tile
        int re4  = (r0 + 1) * n4row;
        float tr0 = g_tr[r0];
        float sv0 = bsum[r0];
        float tr1 = tr0, sv1 = sv0;
        if (re4 < tb4 + cnt4) { tr1 = g_tr[r0 + 1]; sv1 = bsum[r0 + 1]; }

        const float4* sb = buf[bb];
#pragma unroll
        for (int u = 0; u < 4; u++) {
            int idx = tid + u * 256;
            if (idx < cnt4) {
                float4 x = sb[idx];
                int f4 = tb4 + idx;
                bool sec = (f4 >= re4);
                float tr = sec ? tr1 : tr0;
                if (max4(x) > tr) {
                    int row = sec ? (r0 + 1) : r0;
                    scan4(x, 4 * f4, tr, sec ? sv1 : sv0, row * V, V);
                }
            }
        }
        __syncthreads();   // all threads done reading buf[bb]
        if (tid == 0) {
            int tn = t + 2 * G;
            if (tn < nTiles) {
                int tb = tn * TILE4;
                uint32_t bytes = (uint32_t)(min(TILE4, total4 - tb)) * 16u;
                uint32_t mb = bb ? m1 : m0;
                mbar_expect_tx(mb, bytes);
                bulk_g2s(bb ? bs1 : bs0, gbase + tb, bytes, mb);
            }
        }
    }
}

// ---------------- kernel C: exact top-128 selection ----------------
__global__ void k_select(const float* __restrict__ lp, int V, int totalElems) {
    __shared__ unsigned int hist[4096];
    __shared__ unsigned int scanbuf[1024];
    __shared__ int res[2];
    __shared__ int cnt;
    __shared__ unsigned long long sbuf[512];
    int tid = threadIdx.x, bd = blockDim.x;    // bd = 1024
    int C = min(g_cnt, CAP);

    // phase 1: 12-bit histogram of candidate keys
    for (int i = tid; i < 4096; i += bd) hist[i] = 0;
    if (tid == 0) { res[0] = 0; res[1] = 0; cnt = 0; }
    __syncthreads();
    for (int i = tid; i < C; i += bd)
        atomicAdd(&hist[(unsigned int)(g_cand[i] >> 52)], 1u);
    __syncthreads();
    find_bin(hist, 4096, KSEL, scanbuf, res);
    int b1 = res[0];
    int above1 = res[1];
    __syncthreads();

    // phase 2: refine inside bin b1 with next 8 key bits
    for (int i = tid; i < 256; i += bd) hist[i] = 0;
    if (tid == 0) { res[0] = 0; res[1] = 0; }
    __syncthreads();
    for (int i = tid; i < C; i += bd) {
        unsigned long long c = g_cand[i];
        if ((unsigned int)(c >> 52) == (unsigned)b1)
            atomicAdd(&hist[(unsigned int)(c >> 44) & 0xFFu], 1u);
    }
    __syncthreads();
    find_bin(hist, 256, KSEL - above1, scanbuf, res);
    int b2 = res[0];
    __syncthreads();
    unsigned int P = ((unsigned int)b1 << 8) | (unsigned int)b2;  // 20-bit prefix

    // phase 3: collect finalists
    for (int i = tid; i < C; i += bd) {
        unsigned long long c = g_cand[i];
        if ((unsigned int)(c >> 44) >= P) {
            int p = atomicAdd(&cnt, 1);
            if (p < 512) sbuf[p] = c;
        }
    }
    __syncthreads();
    int M = min(cnt, 512);
    int n = (M <= 128) ? 128 : ((M <= 256) ? 256 : 512);
    for (int i = tid; i < n; i += bd)
        if (i >= M) sbuf[i] = 0ULL;
    __syncthreads();

    // bitonic sort descending (value desc, then flat-index asc via ~flat)
    for (int k = 2; k <= n; k <<= 1) {
        for (int j = k >> 1; j > 0; j >>= 1) {
            for (int i = tid; i < n; i += bd) {
                int l = i ^ j;
                if (l > i) {
                    unsigned long long a = sbuf[i], b = sbuf[l];
                    bool up = ((i & k) == 0);
                    if (up == (a < b)) { sbuf[i] = b; sbuf[l] = a; }
                }
            }
            __syncthreads();
        }
    }

    if (tid < KSEL) {
        unsigned long long c = sbuf[tid];
        unsigned int key = (unsigned int)(c >> 32);
        unsigned int flat = ~((unsigned int)c);
        if (flat >= (unsigned)totalElems) flat = 0;   // defensive (padding)
        int q = (int)(flat / (unsigned)V);
        int v = (int)(flat - (unsigned)q * (unsigned)V);
        g_qsel[tid] = q;
        g_tok[tid]  = v;
        g_topp[tid] = fromKey(key);
        float x = lp[(size_t)flat];
        if (v == V - 1) x -= 1000.0f;
        g_loc[tid] = x;
    }
}

// ------- kernel D (vectorized): gather + write all output sections, float4 -------
// Requires B, H powers of two and all section boundaries divisible by 4.
__global__ void k_write4(const int* __restrict__ bseq, const float* __restrict__ bseqlp,
                         const float* __restrict__ sh, const float* __restrict__ sc,
                         float* __restrict__ out,
                         int T, int B, int S, int H, int total4,
                         int bSh, int hSh, int bhSh) {
    int i4 = blockIdx.x * blockDim.x + threadIdx.x;
    if (i4 >= total4) return;
    int idx = i4 * 4;
    int t = g_t;
    int TB = T * B;
    int BH = B * H;
    float4 val;
    if (idx < TB) {                               // new_seq (int -> float)
        int i  = idx >> bSh;
        int b0 = idx & (B - 1);
        if (i < t) {
            val.x = (float)bseq[i * B + g_qsel[b0]];
            val.y = (float)bseq[i * B + g_qsel[b0 + 1]];
            val.z = (float)bseq[i * B + g_qsel[b0 + 2]];
            val.w = (float)bseq[i * B + g_qsel[b0 + 3]];
        } else if (i == t) {
            val.x = (float)g_tok[b0];
            val.y = (float)g_tok[b0 + 1];
            val.z = (float)g_tok[b0 + 2];
            val.w = (float)g_tok[b0 + 3];
        } else {
            val.x = (float)bseq[idx];
            val.y = (float)bseq[idx + 1];
            val.z = (float)bseq[idx + 2];
            val.w = (float)bseq[idx + 3];
        }
    } else if (idx < 2 * TB) {                    // new_logps
        int r  = idx - TB;
        int i  = r >> bSh;
        int b0 = r & (B - 1);
        if (i < t) {
            val.x = bseqlp[i * B + g_qsel[b0]];
            val.y = bseqlp[i * B + g_qsel[b0 + 1]];
            val.z = bseqlp[i * B + g_qsel[b0 + 2]];
            val.w = bseqlp[i * B + g_qsel[b0 + 3]];
        } else if (i == t) {
            val.x = g_loc[b0];
            val.y = g_loc[b0 + 1];
            val.z = g_loc[b0 + 2];
            val.w = g_loc[b0 + 3];
        } else {
            val.x = bseqlp[r];
            val.y = bseqlp[r + 1];
            val.z = bseqlp[r + 2];
            val.w = bseqlp[r + 3];
        }
    } else if (idx < 2 * TB + B) {                // new_sum
        int r = idx - 2 * TB;
        val.x = g_topp[r];
        val.y = g_topp[r + 1];
        val.z = g_topp[r + 2];
        val.w = g_topp[r + 3];
    } else if (idx < 2 * TB + B + S) {            // new_h: aligned float4 gather
        int r  = idx - (2 * TB + B);
        int l  = r >> bhSh;
        int bh = r & (BH - 1);
        int b  = bh >> hSh;
        int h  = bh & (H - 1);
        val = *reinterpret_cast<const float4*>(
            sh + (size_t)l * BH + (size_t)g_qsel[b] * H + h);
    } else {                                      // new_c
        int r  = idx - (2 * TB + B + S);
        int l  = r >> bhSh;
        int bh = r & (BH - 1);
        int b  = bh >> hSh;
        int h  = bh & (H - 1);
        val = *reinterpret_cast<const float4*>(
            sc + (size_t)l * BH + (size_t)g_qsel[b] * H + h);
    }
    *reinterpret_cast<float4*>(out + idx) = val;
}

// ---------------- kernel D (scalar fallback) ----------------
__global__ void k_write(const int* __restrict__ bseq, const float* __restrict__ bseqlp,
                        const float* __restrict__ sh, const float* __restrict__ sc,
                        float* __restrict__ out,
                        int T, int B, int S, int H, int total) {
    int idx = blockIdx.x * blockDim.x + threadIdx.x;
    if (idx >= total) return;
    int t = g_t;
    int TB = T * B;
    int BH = B * H;
    float val = 0.0f;
    if (idx < TB) {
        int i = idx / B, b = idx - i * B;
        int srcv;
        if (i < t)       srcv = bseq[i * B + g_qsel[b]];
        else if (i == t) srcv = g_tok[b];
        else             srcv = bseq[idx];
        val = (float)srcv;
    } else if (idx < 2 * TB) {
        int r = idx - TB;
        int i = r / B, b = r - i * B;
        if (i < t)       val = bseqlp[i * B + g_qsel[b]];
        else if (i == t) val = g_loc[b];
        else             val = bseqlp[r];
    } else if (idx < 2 * TB + B) {
        val = g_topp[idx - 2 * TB];
    } else if (idx < 2 * TB + B + S) {
        int r = idx - (2 * TB + B);
        int l = r / BH;
        int bh = r - l * BH;
        int b = bh / H, h = bh - b * H;
        val = sh[(size_t)l * BH + (size_t)g_qsel[b] * H + h];
    } else {
        int r = idx - (2 * TB + B + S);
        int l = r / BH;
        int bh = r - l * BH;
        int b = bh / H, h = bh - b * H;
        val = sc[(size_t)l * BH + (size_t)g_qsel[b] * H + h];
    }
    out[idx] = val;
}

// ---------------- launch ----------------
static inline int ilog2_exact(int x) {
    int s = 0;
    while ((1 << s) < x) s++;
    return ((1 << s) == x) ? s : -1;
}

extern "C" void kernel_launch(void* const* d_in, const int* in_sizes, int n_in,
                              void* d_out, int out_size) {
    const float* lp     = (const float*)d_in[0];   // (B, V)
    const int*   bseq   = (const int*)  d_in[1];   // (T, B)
    const float* bseqlp = (const float*)d_in[2];   // (T, B)
    const float* bsum   = (const float*)d_in[3];   // (B,)
    const float* sh     = (const float*)d_in[4];   // (L, B, H)
    const float* sc     = (const float*)d_in[5];   // (L, B, H)
    const int*   tptr   = (n_in > 6) ? (const int*)d_in[6] : nullptr;

    int B = in_sizes[3];
    int V = in_sizes[0] / B;
    int T = in_sizes[1] / B;
    int S = in_sizes[4];          // L*B*H
    int H = 1024;                 // fixed for this problem shape

    int n4row  = V >> 2;
    int total4 = B * n4row;
    int nTiles = (total4 + TILE4 - 1) / TILE4;
    int G = GFILT < nTiles ? GFILT : nTiles;

    int bSh  = ilog2_exact(B);
    int hSh  = ilog2_exact(H);
    int bhSh = ilog2_exact(B * H);

    k_prep  <<<SBLK, 256>>>(lp, bsum, tptr, B, V);
    k_filter<<<G, 256>>>(lp, bsum, V, n4row, total4, nTiles);
    k_select<<<1, 1024>>>(lp, V, B * V);

    int total = out_size;
    int TB = T * B;
    bool pw = (bSh >= 0) && (hSh >= 0) && (bhSh >= 0) &&
              (total % 4 == 0) && (TB % 4 == 0) && (B % 4 == 0) && (S % 4 == 0);
    if (pw) {
        int t4 = total / 4;
        k_write4<<<(t4 + 255) / 256, 256>>>(bseq, bseqlp, sh, sc,
                                            (float*)d_out, T, B, S, H, t4,
                                            bSh, hSh, bhSh);
    } else {
        k_write<<<(total + 255) / 256, 256>>>(bseq, bseqlp, sh, sc,
                                              (float*)d_out, T, B, S, H, total);
    }
}